// round 16
// baseline (speedup 1.0000x reference)
#include <cuda_runtime.h>
#include <cuda_bf16.h>
#include <cstdint>
#include <math.h>

#define NN_MAX 100000
#define EE_MAX 1600000
#define DH 64

// ---------------- device scratch ----------------
__device__ float g_tmp[NN_MAX * DH];   // fp32 messages: (act(X) @ W^T) * dinv
__device__ float g_h[NN_MAX * DH];     // layer activations (pre-BN, post-bias)
__device__ float g_dinv[NN_MAX];
__device__ int   g_counts[NN_MAX];     // zeroed by scan3 after use (self-restoring)
__device__ int   g_rowptr[NN_MAX + 1];
__device__ int   g_cursor[NN_MAX];
__device__ int   g_esrc[EE_MAX];
__device__ int   g_blocksums[128];
__device__ float g_sums[3 * DH];       // per-layer BN sums (zeroed by hist_kernel)
__device__ float g_sumsq[3 * DH];

__device__ __forceinline__ float gelu_f(float v) {
    return 0.5f * v * (1.0f + erff(v * 0.70710678118654752440f));
}

__device__ __forceinline__ unsigned int smem_u32(const void* p) {
    unsigned int a;
    asm("{ .reg .u64 t; cvta.to.shared.u64 t, %1; cvt.u32.u64 %0, t; }"
        : "=r"(a) : "l"(p));
    return a;
}

__device__ __forceinline__ void ldmat4(unsigned int& r0, unsigned int& r1,
                                       unsigned int& r2, unsigned int& r3,
                                       unsigned int addr) {
    asm volatile("ldmatrix.sync.aligned.m8n8.x4.shared.b16 {%0,%1,%2,%3}, [%4];"
                 : "=r"(r0), "=r"(r1), "=r"(r2), "=r"(r3) : "r"(addr));
}

__device__ __forceinline__ void mma16816(float* c, const unsigned int* a,
                                         unsigned int b0, unsigned int b1) {
    asm volatile(
        "mma.sync.aligned.m16n8k16.row.col.f32.bf16.bf16.f32 "
        "{%0,%1,%2,%3}, {%4,%5,%6,%7}, {%8,%9}, {%0,%1,%2,%3};"
        : "+f"(c[0]), "+f"(c[1]), "+f"(c[2]), "+f"(c[3])
        : "r"(a[0]), "r"(a[1]), "r"(a[2]), "r"(a[3]), "r"(b0), "r"(b1));
}

__device__ __forceinline__ unsigned int bf2pack(float x, float y) {
    __nv_bfloat162 t = __halves2bfloat162(__float2bfloat16(x), __float2bfloat16(y));
    return *(unsigned int*)&t;
}

// ---------------- CSR build ----------------
// hist also zeroes the per-layer BN stats for this call (block 0).
__global__ void hist_kernel(const int* __restrict__ dst, int ee) {
    if (blockIdx.x == 0 && threadIdx.x < 3 * DH) {
        g_sums[threadIdx.x] = 0.0f;
        g_sumsq[threadIdx.x] = 0.0f;
    }
    int e = blockIdx.x * blockDim.x + threadIdx.x;
    if (e < ee) atomicAdd(&g_counts[dst[e]], 1);
}

// shuffle-based block scan: 256 threads x 4 elems = 1024 per block.
// Writes inclusive-within-block prefix to g_rowptr, block total to g_blocksums.
__global__ void scan1_kernel(int nn) {
    __shared__ int warpsum[8];
    int t = threadIdx.x;
    int base = blockIdx.x * 1024 + t * 4;
    int a0 = 0, a1 = 0, a2 = 0, a3 = 0;
    if (base + 3 < nn) {
        int4 v = *(const int4*)&g_counts[base];
        a0 = v.x; a1 = v.y; a2 = v.z; a3 = v.w;
    } else {
        if (base + 0 < nn) a0 = g_counts[base + 0];
        if (base + 1 < nn) a1 = g_counts[base + 1];
        if (base + 2 < nn) a2 = g_counts[base + 2];
        if (base + 3 < nn) a3 = g_counts[base + 3];
    }
    int s1 = a0 + a1, s2 = s1 + a2, s3 = s2 + a3;
    int lane = t & 31, warp = t >> 5;
    int x = s3;
#pragma unroll
    for (int off = 1; off < 32; off <<= 1) {
        int y = __shfl_up_sync(0xffffffffu, x, off);
        if (lane >= off) x += y;
    }
    if (lane == 31) warpsum[warp] = x;
    __syncthreads();
    if (warp == 0 && lane < 8) {
        int w = warpsum[lane];
#pragma unroll
        for (int off = 1; off < 8; off <<= 1) {
            int y = __shfl_up_sync(0xffu, w, off);
            if (lane >= off) w += y;
        }
        warpsum[lane] = w;
    }
    __syncthreads();
    int pre = ((warp > 0) ? warpsum[warp - 1] : 0) + (x - s3);
    int r0 = pre + a0, r1 = pre + s1, r2 = pre + s2, r3 = pre + s3;
    if (base + 3 < nn) {
        *(int4*)&g_rowptr[base] = make_int4(r0, r1, r2, r3);
    } else {
        if (base + 0 < nn) g_rowptr[base + 0] = r0;
        if (base + 1 < nn) g_rowptr[base + 1] = r1;
        if (base + 2 < nn) g_rowptr[base + 2] = r2;
        if (base + 3 < nn) g_rowptr[base + 3] = r3;
    }
    if (t == 255) g_blocksums[blockIdx.x] = pre + s3;
}

__global__ void scan3_kernel(int nn, int ee, int nb) {
    __shared__ int bs[128];
    int t = threadIdx.x;
    if (t < 128) bs[t] = (t < nb) ? g_blocksums[t] : 0;
    __syncthreads();
    for (int off = 1; off < 128; off <<= 1) {
        int v = (t >= off && t < 128) ? bs[t - off] : 0;
        __syncthreads();
        if (t < 128) bs[t] += v;
        __syncthreads();
    }
    int base = (blockIdx.x == 0) ? 0 : bs[blockIdx.x - 1];

    int i = blockIdx.x * 1024 + t;
    if (i < nn) {
        int c = g_counts[i];
        g_counts[i] = 0;
        int excl = g_rowptr[i] - c + base;
        g_rowptr[i] = excl;
        g_cursor[i] = excl;
        g_dinv[i] = rsqrtf((float)(c + 1));  // +1 self loop
    }
    if (i == 0) g_rowptr[nn] = ee;
}

// ---------------- GEMM via tensor cores (split-bf16, 3 MMAs) ----------------
// WITH_FILL: trailing blocks run CSR fill (horizontal fusion with layer-1 GEMM).
template <int DIN, bool USE_GH, bool APPLY_ACT, bool WITH_FILL>
__global__ __launch_bounds__(256)
void gemm_scale_kernel(const float* __restrict__ Xin,
                       const float* __restrict__ W, int nn,
                       const float* __restrict__ gamma,
                       const float* __restrict__ beta,
                       float invN, int statsIdx,
                       const int* __restrict__ fsrc,
                       const int* __restrict__ fdst,
                       int ee, int gemmBlocks) {
    if (WITH_FILL && (int)blockIdx.x >= gemmBlocks) {
        int e = ((int)blockIdx.x - gemmBlocks) * 256 + threadIdx.x;
        if (e < ee) {
            int pos = atomicAdd(&g_cursor[fdst[e]], 1);
            g_esrc[pos] = fsrc[e];
        }
        return;
    }

    const float* __restrict__ X = USE_GH ? (const float*)g_h : Xin;
    const int NST = DIN / 32;

    __shared__ __align__(16) __nv_bfloat162 AsHi[128][20];
    __shared__ __align__(16) __nv_bfloat162 AsLo[128][20];
    __shared__ __align__(16) __nv_bfloat162 BsHi[64][20];
    __shared__ __align__(16) __nv_bfloat162 BsLo[64][20];
    __shared__ float s_sc[DH];
    __shared__ float s_sh[DH];

    int tid = threadIdx.x;
    int lane = tid & 31;
    int wid = tid >> 5;
    int br = blockIdx.x * 128;
    int m0w = (wid & 3) * 32;
    int n0w = (wid >> 2) * 32;

    if (APPLY_ACT) {
        if (tid < DH) {
            float mean = g_sums[statsIdx * DH + tid] * invN;
            float var = g_sumsq[statsIdx * DH + tid] * invN - mean * mean;
            float sc = gamma[tid] * rsqrtf(var + 1e-5f);
            s_sc[tid] = sc;
            s_sh[tid] = beta[tid] - mean * sc;
        }
        __syncthreads();
    }

    unsigned int asHiB = smem_u32(AsHi);
    unsigned int asLoB = smem_u32(AsLo);
    unsigned int bsHiB = smem_u32(BsHi);
    unsigned int bsLoB = smem_u32(BsLo);

    float acc[2][4][4];
#pragma unroll
    for (int mi = 0; mi < 2; mi++) {
#pragma unroll
        for (int ni = 0; ni < 4; ni++) {
#pragma unroll
            for (int q = 0; q < 4; q++) acc[mi][ni][q] = 0.0f;
        }
    }

    int arow = tid >> 1;
    int aseg = (tid & 1) * 16;
    int bj = tid & 63;
    int bkh = (tid >> 6) * 8;

    for (int s = 0; s < NST; s++) {
        int kb = s * 32;
        // ---- stage A (X) ----
        {
            int row = br + arow;
            bool ok = row < nn;
            const float* xr = X + (size_t)row * DIN + kb + aseg;
            char* rowHi = (char*)&AsHi[arow][0] + aseg * 2;
            char* rowLo = (char*)&AsLo[arow][0] + aseg * 2;
#pragma unroll
            for (int half = 0; half < 2; half++) {
                unsigned int hw_[4];
                unsigned int lw_[4];
#pragma unroll
                for (int kk2 = 0; kk2 < 2; kk2++) {
                    int kk = half * 2 + kk2;
                    float4 v = ok ? *(const float4*)(xr + kk * 4)
                                  : make_float4(0.f, 0.f, 0.f, 0.f);
                    if (APPLY_ACT && ok) {
                        int k0 = kb + aseg + kk * 4;
                        v.x = gelu_f(v.x * s_sc[k0 + 0] + s_sh[k0 + 0]);
                        v.y = gelu_f(v.y * s_sc[k0 + 1] + s_sh[k0 + 1]);
                        v.z = gelu_f(v.z * s_sc[k0 + 2] + s_sh[k0 + 2]);
                        v.w = gelu_f(v.w * s_sc[k0 + 3] + s_sh[k0 + 3]);
                    }
                    float hx = __bfloat162float(__float2bfloat16(v.x));
                    float hy = __bfloat162float(__float2bfloat16(v.y));
                    float hz = __bfloat162float(__float2bfloat16(v.z));
                    float hw = __bfloat162float(__float2bfloat16(v.w));
                    hw_[kk2 * 2 + 0] = bf2pack(hx, hy);
                    hw_[kk2 * 2 + 1] = bf2pack(hz, hw);
                    lw_[kk2 * 2 + 0] = bf2pack(v.x - hx, v.y - hy);
                    lw_[kk2 * 2 + 1] = bf2pack(v.z - hz, v.w - hw);
                }
                *(uint4*)(rowHi + half * 16) = make_uint4(hw_[0], hw_[1], hw_[2], hw_[3]);
                *(uint4*)(rowLo + half * 16) = make_uint4(lw_[0], lw_[1], lw_[2], lw_[3]);
            }
        }
        // ---- stage B (W) ----
        {
            const float* wr = W + (size_t)bj * DIN + kb + bkh;
            unsigned int hw_[4];
            unsigned int lw_[4];
#pragma unroll
            for (int kk = 0; kk < 2; kk++) {
                float4 v = *(const float4*)(wr + kk * 4);
                float hx = __bfloat162float(__float2bfloat16(v.x));
                float hy = __bfloat162float(__float2bfloat16(v.y));
                float hz = __bfloat162float(__float2bfloat16(v.z));
                float hw = __bfloat162float(__float2bfloat16(v.w));
                hw_[kk * 2 + 0] = bf2pack(hx, hy);
                hw_[kk * 2 + 1] = bf2pack(hz, hw);
                lw_[kk * 2 + 0] = bf2pack(v.x - hx, v.y - hy);
                lw_[kk * 2 + 1] = bf2pack(v.z - hz, v.w - hw);
            }
            *(uint4*)((char*)&BsHi[bj][0] + bkh * 2) =
                make_uint4(hw_[0], hw_[1], hw_[2], hw_[3]);
            *(uint4*)((char*)&BsLo[bj][0] + bkh * 2) =
                make_uint4(lw_[0], lw_[1], lw_[2], lw_[3]);
        }
        __syncthreads();

#pragma unroll
        for (int ks = 0; ks < 2; ks++) {
            unsigned int ahi[2][4];
            unsigned int alo[2][4];
#pragma unroll
            for (int mi = 0; mi < 2; mi++) {
                unsigned int roff =
                    (unsigned int)(m0w + mi * 16 + (lane & 15)) * 80u +
                    (unsigned int)(ks * 16 + ((lane >> 4) << 3)) * 2u;
                ldmat4(ahi[mi][0], ahi[mi][1], ahi[mi][2], ahi[mi][3], asHiB + roff);
                ldmat4(alo[mi][0], alo[mi][1], alo[mi][2], alo[mi][3], asLoB + roff);
            }
            unsigned int bhi[2][4];
            unsigned int blo[2][4];
#pragma unroll
            for (int pi = 0; pi < 2; pi++) {
                unsigned int roff =
                    (unsigned int)(n0w + pi * 16 + (((lane >> 4) & 1) << 3) +
                                   (lane & 7)) * 80u +
                    (unsigned int)(ks * 16 + (((lane >> 3) & 1) << 3)) * 2u;
                ldmat4(bhi[pi][0], bhi[pi][1], bhi[pi][2], bhi[pi][3], bsHiB + roff);
                ldmat4(blo[pi][0], blo[pi][1], blo[pi][2], blo[pi][3], bsLoB + roff);
            }
#pragma unroll
            for (int mi = 0; mi < 2; mi++) {
#pragma unroll
                for (int ni = 0; ni < 4; ni++) {
                    int pi = ni >> 1;
                    int sel = (ni & 1) * 2;
                    mma16816(acc[mi][ni], ahi[mi], bhi[pi][sel], bhi[pi][sel + 1]);
                    mma16816(acc[mi][ni], ahi[mi], blo[pi][sel], blo[pi][sel + 1]);
                    mma16816(acc[mi][ni], alo[mi], bhi[pi][sel], bhi[pi][sel + 1]);
                }
            }
        }
        __syncthreads();
    }

#pragma unroll
    for (int mi = 0; mi < 2; mi++) {
        int r0 = br + m0w + mi * 16 + (lane >> 2);
        int r1 = r0 + 8;
        float dv0 = (r0 < nn) ? g_dinv[r0] : 0.0f;
        float dv1 = (r1 < nn) ? g_dinv[r1] : 0.0f;
#pragma unroll
        for (int ni = 0; ni < 4; ni++) {
            int c = n0w + ni * 8 + (lane & 3) * 2;
            if (r0 < nn) {
                float2 o = make_float2(acc[mi][ni][0] * dv0, acc[mi][ni][1] * dv0);
                *(float2*)&g_tmp[(size_t)r0 * DH + c] = o;
            }
            if (r1 < nn) {
                float2 o = make_float2(acc[mi][ni][2] * dv1, acc[mi][ni][3] * dv1);
                *(float2*)&g_tmp[(size_t)r1 * DH + c] = o;
            }
        }
    }
}

// ---------------- gather-aggregate + bias + BN stats (R14 form — FROZEN) ----------------
__global__ void gather_kernel(const float* __restrict__ bias, int nn, int statsIdx) {
    __shared__ float ss[DH];
    __shared__ float sq[DH];
    int tid = threadIdx.x;
    if (tid < DH) { ss[tid] = 0.0f; sq[tid] = 0.0f; }
    __syncthreads();

    const float2* __restrict__ tmp2 = (const float2*)g_tmp;
    float2* __restrict__ h2 = (float2*)g_h;

    int lane = tid & 31;
    int warp = blockIdx.x * (blockDim.x >> 5) + (tid >> 5);
    int nwarps = gridDim.x * (blockDim.x >> 5);

    float bx = bias[2 * lane];
    float by = bias[2 * lane + 1];
    float s0 = 0.f, s1 = 0.f, q0 = 0.f, q1 = 0.f;

    for (int n = warp; n < nn; n += nwarps) {
        int st = g_rowptr[n];
        int en = g_rowptr[n + 1];
        float2 self = tmp2[n * 32 + lane];
        float ax = self.x, ay = self.y;
        int e = st;
        for (; e < en && (e & 3); e++) {
            float2 v = tmp2[g_esrc[e] * 32 + lane];
            ax += v.x; ay += v.y;
        }
        for (; e + 8 <= en; e += 8) {
            int4 i0 = *(const int4*)&g_esrc[e];
            int4 i1 = *(const int4*)&g_esrc[e + 4];
            float2 v0 = tmp2[i0.x * 32 + lane];
            float2 v1 = tmp2[i0.y * 32 + lane];
            float2 v2 = tmp2[i0.z * 32 + lane];
            float2 v3 = tmp2[i0.w * 32 + lane];
            float2 v4 = tmp2[i1.x * 32 + lane];
            float2 v5 = tmp2[i1.y * 32 + lane];
            float2 v6 = tmp2[i1.z * 32 + lane];
            float2 v7 = tmp2[i1.w * 32 + lane];
            ax += ((v0.x + v1.x) + (v2.x + v3.x)) + ((v4.x + v5.x) + (v6.x + v7.x));
            ay += ((v0.y + v1.y) + (v2.y + v3.y)) + ((v4.y + v5.y) + (v6.y + v7.y));
        }
        for (; e < en; e++) {
            float2 v = tmp2[g_esrc[e] * 32 + lane];
            ax += v.x; ay += v.y;
        }
        float dv = g_dinv[n];
        float rx = ax * dv + bx;
        float ry = ay * dv + by;
        h2[n * 32 + lane] = make_float2(rx, ry);
        s0 += rx; q0 += rx * rx;
        s1 += ry; q1 += ry * ry;
    }

    atomicAdd(&ss[2 * lane], s0);
    atomicAdd(&ss[2 * lane + 1], s1);
    atomicAdd(&sq[2 * lane], q0);
    atomicAdd(&sq[2 * lane + 1], q1);
    __syncthreads();
    if (tid < DH) {
        atomicAdd(&g_sums[statsIdx * DH + tid], ss[tid]);
        atomicAdd(&g_sumsq[statsIdx * DH + tid], sq[tid]);
    }
}

// ---------------- final: out = act(h) @ Wf^T + bf  (64 -> 10) ----------------
__global__ void final_kernel(const float* __restrict__ Wf, const float* __restrict__ bf,
                             float* __restrict__ out, int nn,
                             const float* __restrict__ gamma,
                             const float* __restrict__ beta, float invN) {
    __shared__ float Hs[64][65];
    __shared__ float Ws[10][64];
    __shared__ float s_sc[DH];
    __shared__ float s_sh[DH];
    int tid = threadIdx.x;  // 128 threads
    int br = blockIdx.x * 64;

    if (tid < DH) {
        float mean = g_sums[2 * DH + tid] * invN;
        float var = g_sumsq[2 * DH + tid] * invN - mean * mean;
        float sc = gamma[tid] * rsqrtf(var + 1e-5f);
        s_sc[tid] = sc;
        s_sh[tid] = beta[tid] - mean * sc;
    }
    __syncthreads();

    for (int idx = tid; idx < 64 * 64; idx += 128) {
        int n = idx >> 6;
        int k = idx & 63;
        int row = br + n;
        float v = (row < nn) ? g_h[row * DH + k] : 0.0f;
        Hs[n][k] = gelu_f(v * s_sc[k] + s_sh[k]);
    }
    for (int idx = tid; idx < 640; idx += 128) {
        Ws[idx >> 6][idx & 63] = Wf[idx];
    }
    __syncthreads();

    int nl = tid & 63;
    int c0 = (tid >> 6) * 5;
    float acc[5];
#pragma unroll
    for (int c = 0; c < 5; c++) acc[c] = bf[c0 + c];
#pragma unroll 16
    for (int k = 0; k < 64; k++) {
        float hv = Hs[nl][k];
#pragma unroll
        for (int c = 0; c < 5; c++) acc[c] += hv * Ws[c0 + c][k];
    }
    int row = br + nl;
    if (row < nn) {
#pragma unroll
        for (int c = 0; c < 5; c++) out[row * 10 + c0 + c] = acc[c];
    }
}

// ---------------- host orchestration ----------------
extern "C" void kernel_launch(void* const* d_in, const int* in_sizes, int n_in,
                              void* d_out, int out_size) {
    const float* x  = (const float*)d_in[0];
    const int*   ei = (const int*)d_in[1];
    const float* W1 = (const float*)d_in[2];
    const float* b1 = (const float*)d_in[3];
    const float* g1 = (const float*)d_in[4];
    const float* be1 = (const float*)d_in[5];
    const float* W2 = (const float*)d_in[6];
    const float* b2 = (const float*)d_in[7];
    const float* g2 = (const float*)d_in[8];
    const float* be2 = (const float*)d_in[9];
    const float* W3 = (const float*)d_in[10];
    const float* b3 = (const float*)d_in[11];
    const float* g3 = (const float*)d_in[12];
    const float* be3 = (const float*)d_in[13];
    const float* Wf = (const float*)d_in[14];
    const float* bf = (const float*)d_in[15];
    float* out = (float*)d_out;

    int nn = in_sizes[0] / 128;      // 100000
    int ee = in_sizes[1] / 2;        // 1600000
    const int* src = ei;
    const int* dst = ei + ee;

    int nb_e = (ee + 255) / 256;
    int nb_scan = (nn + 1023) / 1024;
    float invN = 1.0f / (float)nn;

    int gemm_blocks = (nn + 127) / 128;
    int out_blocks = (nn + 63) / 64;
    int gather_blocks = 1184;

    // ---- CSR build (also zeroes BN stats for this call) ----
    hist_kernel<<<nb_e, 256>>>(dst, ee);
    scan1_kernel<<<nb_scan, 256>>>(nn);
    scan3_kernel<<<nb_scan, 1024>>>(nn, ee, nb_scan);

    // ---- layer 1 (128 -> 64), fused with CSR fill (trailing blocks) ----
    gemm_scale_kernel<128, false, false, true><<<gemm_blocks + nb_e, 256>>>(
        x, W1, nn, nullptr, nullptr, 0.0f, 0, src, dst, ee, gemm_blocks);
    gather_kernel<<<gather_blocks, 256>>>(b1, nn, 0);

    // ---- layer 2 (64 -> 64): BN1+GELU fused into X staging ----
    gemm_scale_kernel<64, true, true, false><<<gemm_blocks, 256>>>(
        nullptr, W2, nn, g1, be1, invN, 0, nullptr, nullptr, 0, gemm_blocks);
    gather_kernel<<<gather_blocks, 256>>>(b2, nn, 1);

    // ---- layer 3 (64 -> 64): BN2+GELU fused into X staging ----
    gemm_scale_kernel<64, true, true, false><<<gemm_blocks, 256>>>(
        nullptr, W3, nn, g2, be2, invN, 1, nullptr, nullptr, 0, gemm_blocks);
    gather_kernel<<<gather_blocks, 256>>>(b3, nn, 2);

    // ---- final classifier (64 -> 10): BN3+GELU fused into H load ----
    final_kernel<<<out_blocks, 128>>>(Wf, bf, out, nn, g3, be3, invN);
}

// round 17
// speedup vs baseline: 1.4215x; 1.4215x over previous
#include <cuda_runtime.h>
#include <cuda_bf16.h>
#include <cstdint>
#include <math.h>

#define NN_MAX 100000
#define EE_MAX 1600000
#define DH 64

// ---------------- device scratch ----------------
__device__ float g_tmp[NN_MAX * DH];   // fp32 messages: (act(X) @ W^T) * dinv
__device__ float g_h[NN_MAX * DH];     // layer activations (pre-BN, post-bias)
__device__ float g_dinv[NN_MAX];
__device__ int   g_counts[NN_MAX];     // zeroed by scan3 after use (self-restoring)
__device__ int   g_rowptr[NN_MAX + 1];
__device__ int   g_cursor[NN_MAX];
__device__ int   g_esrc[EE_MAX];
__device__ int   g_blocksums[128];
__device__ float g_sums[3 * DH];       // per-layer BN sums (zeroed by hist_kernel)
__device__ float g_sumsq[3 * DH];

__device__ __forceinline__ float gelu_f(float v) {
    return 0.5f * v * (1.0f + erff(v * 0.70710678118654752440f));
}

__device__ __forceinline__ unsigned int smem_u32(const void* p) {
    unsigned int a;
    asm("{ .reg .u64 t; cvta.to.shared.u64 t, %1; cvt.u32.u64 %0, t; }"
        : "=r"(a) : "l"(p));
    return a;
}

__device__ __forceinline__ void ldmat4(unsigned int& r0, unsigned int& r1,
                                       unsigned int& r2, unsigned int& r3,
                                       unsigned int addr) {
    asm volatile("ldmatrix.sync.aligned.m8n8.x4.shared.b16 {%0,%1,%2,%3}, [%4];"
                 : "=r"(r0), "=r"(r1), "=r"(r2), "=r"(r3) : "r"(addr));
}

__device__ __forceinline__ void mma16816(float* c, const unsigned int* a,
                                         unsigned int b0, unsigned int b1) {
    asm volatile(
        "mma.sync.aligned.m16n8k16.row.col.f32.bf16.bf16.f32 "
        "{%0,%1,%2,%3}, {%4,%5,%6,%7}, {%8,%9}, {%0,%1,%2,%3};"
        : "+f"(c[0]), "+f"(c[1]), "+f"(c[2]), "+f"(c[3])
        : "r"(a[0]), "r"(a[1]), "r"(a[2]), "r"(a[3]), "r"(b0), "r"(b1));
}

__device__ __forceinline__ unsigned int bf2pack(float x, float y) {
    __nv_bfloat162 t = __halves2bfloat162(__float2bfloat16(x), __float2bfloat16(y));
    return *(unsigned int*)&t;
}

// ---------------- CSR build ----------------
// hist also zeroes the per-layer BN stats for this call (block 0).
__global__ void hist_kernel(const int* __restrict__ dst, int ee) {
    if (blockIdx.x == 0 && threadIdx.x < 3 * DH) {
        g_sums[threadIdx.x] = 0.0f;
        g_sumsq[threadIdx.x] = 0.0f;
    }
    int e = blockIdx.x * blockDim.x + threadIdx.x;
    if (e < ee) atomicAdd(&g_counts[dst[e]], 1);
}

// shuffle-based block scan: 256 threads x 4 elems = 1024 per block.
__global__ void scan1_kernel(int nn) {
    __shared__ int warpsum[8];
    int t = threadIdx.x;
    int base = blockIdx.x * 1024 + t * 4;
    int a0 = 0, a1 = 0, a2 = 0, a3 = 0;
    if (base + 3 < nn) {
        int4 v = *(const int4*)&g_counts[base];
        a0 = v.x; a1 = v.y; a2 = v.z; a3 = v.w;
    } else {
        if (base + 0 < nn) a0 = g_counts[base + 0];
        if (base + 1 < nn) a1 = g_counts[base + 1];
        if (base + 2 < nn) a2 = g_counts[base + 2];
        if (base + 3 < nn) a3 = g_counts[base + 3];
    }
    int s1 = a0 + a1, s2 = s1 + a2, s3 = s2 + a3;
    int lane = t & 31, warp = t >> 5;
    int x = s3;
#pragma unroll
    for (int off = 1; off < 32; off <<= 1) {
        int y = __shfl_up_sync(0xffffffffu, x, off);
        if (lane >= off) x += y;
    }
    if (lane == 31) warpsum[warp] = x;
    __syncthreads();
    if (warp == 0 && lane < 8) {
        int w = warpsum[lane];
#pragma unroll
        for (int off = 1; off < 8; off <<= 1) {
            int y = __shfl_up_sync(0xffu, w, off);
            if (lane >= off) w += y;
        }
        warpsum[lane] = w;
    }
    __syncthreads();
    int pre = ((warp > 0) ? warpsum[warp - 1] : 0) + (x - s3);
    int r0 = pre + a0, r1 = pre + s1, r2 = pre + s2, r3 = pre + s3;
    if (base + 3 < nn) {
        *(int4*)&g_rowptr[base] = make_int4(r0, r1, r2, r3);
    } else {
        if (base + 0 < nn) g_rowptr[base + 0] = r0;
        if (base + 1 < nn) g_rowptr[base + 1] = r1;
        if (base + 2 < nn) g_rowptr[base + 2] = r2;
        if (base + 3 < nn) g_rowptr[base + 3] = r3;
    }
    if (t == 255) g_blocksums[blockIdx.x] = pre + s3;
}

__global__ void scan3_kernel(int nn, int ee, int nb) {
    __shared__ int bs[128];
    int t = threadIdx.x;
    if (t < 128) bs[t] = (t < nb) ? g_blocksums[t] : 0;
    __syncthreads();
    for (int off = 1; off < 128; off <<= 1) {
        int v = (t >= off && t < 128) ? bs[t - off] : 0;
        __syncthreads();
        if (t < 128) bs[t] += v;
        __syncthreads();
    }
    int base = (blockIdx.x == 0) ? 0 : bs[blockIdx.x - 1];

    int i = blockIdx.x * 1024 + t;
    if (i < nn) {
        int c = g_counts[i];
        g_counts[i] = 0;
        int excl = g_rowptr[i] - c + base;
        g_rowptr[i] = excl;
        g_cursor[i] = excl;
        g_dinv[i] = rsqrtf((float)(c + 1));  // +1 self loop
    }
    if (i == 0) g_rowptr[nn] = ee;
}

__global__ void fill_kernel(const int* __restrict__ src, const int* __restrict__ dst, int ee) {
    int e = blockIdx.x * blockDim.x + threadIdx.x;
    if (e < ee) {
        int pos = atomicAdd(&g_cursor[dst[e]], 1);
        g_esrc[pos] = src[e];
    }
}

// ---------------- GEMM via tensor cores (split-bf16, 3 MMAs) ----------------
template <int DIN, bool USE_GH, bool APPLY_ACT>
__global__ __launch_bounds__(256)
void gemm_scale_kernel(const float* __restrict__ Xin,
                       const float* __restrict__ W, int nn,
                       const float* __restrict__ gamma,
                       const float* __restrict__ beta,
                       float invN, int statsIdx) {
    const float* __restrict__ X = USE_GH ? (const float*)g_h : Xin;
    const int NST = DIN / 32;

    __shared__ __align__(16) __nv_bfloat162 AsHi[128][20];
    __shared__ __align__(16) __nv_bfloat162 AsLo[128][20];
    __shared__ __align__(16) __nv_bfloat162 BsHi[64][20];
    __shared__ __align__(16) __nv_bfloat162 BsLo[64][20];
    __shared__ float s_sc[DH];
    __shared__ float s_sh[DH];

    int tid = threadIdx.x;
    int lane = tid & 31;
    int wid = tid >> 5;
    int br = blockIdx.x * 128;
    int m0w = (wid & 3) * 32;
    int n0w = (wid >> 2) * 32;

    if (APPLY_ACT) {
        if (tid < DH) {
            float mean = g_sums[statsIdx * DH + tid] * invN;
            float var = g_sumsq[statsIdx * DH + tid] * invN - mean * mean;
            float sc = gamma[tid] * rsqrtf(var + 1e-5f);
            s_sc[tid] = sc;
            s_sh[tid] = beta[tid] - mean * sc;
        }
        __syncthreads();
    }

    unsigned int asHiB = smem_u32(AsHi);
    unsigned int asLoB = smem_u32(AsLo);
    unsigned int bsHiB = smem_u32(BsHi);
    unsigned int bsLoB = smem_u32(BsLo);

    float acc[2][4][4];
#pragma unroll
    for (int mi = 0; mi < 2; mi++) {
#pragma unroll
        for (int ni = 0; ni < 4; ni++) {
#pragma unroll
            for (int q = 0; q < 4; q++) acc[mi][ni][q] = 0.0f;
        }
    }

    int arow = tid >> 1;
    int aseg = (tid & 1) * 16;
    int bj = tid & 63;
    int bkh = (tid >> 6) * 8;

    for (int s = 0; s < NST; s++) {
        int kb = s * 32;
        // ---- stage A (X) ----
        {
            int row = br + arow;
            bool ok = row < nn;
            const float* xr = X + (size_t)row * DIN + kb + aseg;
            char* rowHi = (char*)&AsHi[arow][0] + aseg * 2;
            char* rowLo = (char*)&AsLo[arow][0] + aseg * 2;
#pragma unroll
            for (int half = 0; half < 2; half++) {
                unsigned int hw_[4];
                unsigned int lw_[4];
#pragma unroll
                for (int kk2 = 0; kk2 < 2; kk2++) {
                    int kk = half * 2 + kk2;
                    float4 v = ok ? *(const float4*)(xr + kk * 4)
                                  : make_float4(0.f, 0.f, 0.f, 0.f);
                    if (APPLY_ACT && ok) {
                        int k0 = kb + aseg + kk * 4;
                        v.x = gelu_f(v.x * s_sc[k0 + 0] + s_sh[k0 + 0]);
                        v.y = gelu_f(v.y * s_sc[k0 + 1] + s_sh[k0 + 1]);
                        v.z = gelu_f(v.z * s_sc[k0 + 2] + s_sh[k0 + 2]);
                        v.w = gelu_f(v.w * s_sc[k0 + 3] + s_sh[k0 + 3]);
                    }
                    float hx = __bfloat162float(__float2bfloat16(v.x));
                    float hy = __bfloat162float(__float2bfloat16(v.y));
                    float hz = __bfloat162float(__float2bfloat16(v.z));
                    float hw = __bfloat162float(__float2bfloat16(v.w));
                    hw_[kk2 * 2 + 0] = bf2pack(hx, hy);
                    hw_[kk2 * 2 + 1] = bf2pack(hz, hw);
                    lw_[kk2 * 2 + 0] = bf2pack(v.x - hx, v.y - hy);
                    lw_[kk2 * 2 + 1] = bf2pack(v.z - hz, v.w - hw);
                }
                *(uint4*)(rowHi + half * 16) = make_uint4(hw_[0], hw_[1], hw_[2], hw_[3]);
                *(uint4*)(rowLo + half * 16) = make_uint4(lw_[0], lw_[1], lw_[2], lw_[3]);
            }
        }
        // ---- stage B (W) ----
        {
            const float* wr = W + (size_t)bj * DIN + kb + bkh;
            unsigned int hw_[4];
            unsigned int lw_[4];
#pragma unroll
            for (int kk = 0; kk < 2; kk++) {
                float4 v = *(const float4*)(wr + kk * 4);
                float hx = __bfloat162float(__float2bfloat16(v.x));
                float hy = __bfloat162float(__float2bfloat16(v.y));
                float hz = __bfloat162float(__float2bfloat16(v.z));
                float hw = __bfloat162float(__float2bfloat16(v.w));
                hw_[kk * 2 + 0] = bf2pack(hx, hy);
                hw_[kk * 2 + 1] = bf2pack(hz, hw);
                lw_[kk * 2 + 0] = bf2pack(v.x - hx, v.y - hy);
                lw_[kk * 2 + 1] = bf2pack(v.z - hz, v.w - hw);
            }
            *(uint4*)((char*)&BsHi[bj][0] + bkh * 2) =
                make_uint4(hw_[0], hw_[1], hw_[2], hw_[3]);
            *(uint4*)((char*)&BsLo[bj][0] + bkh * 2) =
                make_uint4(lw_[0], lw_[1], lw_[2], lw_[3]);
        }
        __syncthreads();

#pragma unroll
        for (int ks = 0; ks < 2; ks++) {
            unsigned int ahi[2][4];
            unsigned int alo[2][4];
#pragma unroll
            for (int mi = 0; mi < 2; mi++) {
                unsigned int roff =
                    (unsigned int)(m0w + mi * 16 + (lane & 15)) * 80u +
                    (unsigned int)(ks * 16 + ((lane >> 4) << 3)) * 2u;
                ldmat4(ahi[mi][0], ahi[mi][1], ahi[mi][2], ahi[mi][3], asHiB + roff);
                ldmat4(alo[mi][0], alo[mi][1], alo[mi][2], alo[mi][3], asLoB + roff);
            }
            unsigned int bhi[2][4];
            unsigned int blo[2][4];
#pragma unroll
            for (int pi = 0; pi < 2; pi++) {
                unsigned int roff =
                    (unsigned int)(n0w + pi * 16 + (((lane >> 4) & 1) << 3) +
                                   (lane & 7)) * 80u +
                    (unsigned int)(ks * 16 + (((lane >> 3) & 1) << 3)) * 2u;
                ldmat4(bhi[pi][0], bhi[pi][1], bhi[pi][2], bhi[pi][3], bsHiB + roff);
                ldmat4(blo[pi][0], blo[pi][1], blo[pi][2], blo[pi][3], bsLoB + roff);
            }
#pragma unroll
            for (int mi = 0; mi < 2; mi++) {
#pragma unroll
                for (int ni = 0; ni < 4; ni++) {
                    int pi = ni >> 1;
                    int sel = (ni & 1) * 2;
                    mma16816(acc[mi][ni], ahi[mi], bhi[pi][sel], bhi[pi][sel + 1]);
                    mma16816(acc[mi][ni], ahi[mi], blo[pi][sel], blo[pi][sel + 1]);
                    mma16816(acc[mi][ni], alo[mi], bhi[pi][sel], bhi[pi][sel + 1]);
                }
            }
        }
        __syncthreads();
    }

#pragma unroll
    for (int mi = 0; mi < 2; mi++) {
        int r0 = br + m0w + mi * 16 + (lane >> 2);
        int r1 = r0 + 8;
        float dv0 = (r0 < nn) ? g_dinv[r0] : 0.0f;
        float dv1 = (r1 < nn) ? g_dinv[r1] : 0.0f;
#pragma unroll
        for (int ni = 0; ni < 4; ni++) {
            int c = n0w + ni * 8 + (lane & 3) * 2;
            if (r0 < nn) {
                float2 o = make_float2(acc[mi][ni][0] * dv0, acc[mi][ni][1] * dv0);
                *(float2*)&g_tmp[(size_t)r0 * DH + c] = o;
            }
            if (r1 < nn) {
                float2 o = make_float2(acc[mi][ni][2] * dv1, acc[mi][ni][3] * dv1);
                *(float2*)&g_tmp[(size_t)r1 * DH + c] = o;
            }
        }
    }
}

// ---------------- gather-aggregate + bias + BN stats (R14 form — FROZEN) ----------------
__global__ void gather_kernel(const float* __restrict__ bias, int nn, int statsIdx) {
    __shared__ float ss[DH];
    __shared__ float sq[DH];
    int tid = threadIdx.x;
    if (tid < DH) { ss[tid] = 0.0f; sq[tid] = 0.0f; }
    __syncthreads();

    const float2* __restrict__ tmp2 = (const float2*)g_tmp;
    float2* __restrict__ h2 = (float2*)g_h;

    int lane = tid & 31;
    int warp = blockIdx.x * (blockDim.x >> 5) + (tid >> 5);
    int nwarps = gridDim.x * (blockDim.x >> 5);

    float bx = bias[2 * lane];
    float by = bias[2 * lane + 1];
    float s0 = 0.f, s1 = 0.f, q0 = 0.f, q1 = 0.f;

    for (int n = warp; n < nn; n += nwarps) {
        int st = g_rowptr[n];
        int en = g_rowptr[n + 1];
        float2 self = tmp2[n * 32 + lane];
        float ax = self.x, ay = self.y;
        int e = st;
        for (; e < en && (e & 3); e++) {
            float2 v = tmp2[g_esrc[e] * 32 + lane];
            ax += v.x; ay += v.y;
        }
        for (; e + 8 <= en; e += 8) {
            int4 i0 = *(const int4*)&g_esrc[e];
            int4 i1 = *(const int4*)&g_esrc[e + 4];
            float2 v0 = tmp2[i0.x * 32 + lane];
            float2 v1 = tmp2[i0.y * 32 + lane];
            float2 v2 = tmp2[i0.z * 32 + lane];
            float2 v3 = tmp2[i0.w * 32 + lane];
            float2 v4 = tmp2[i1.x * 32 + lane];
            float2 v5 = tmp2[i1.y * 32 + lane];
            float2 v6 = tmp2[i1.z * 32 + lane];
            float2 v7 = tmp2[i1.w * 32 + lane];
            ax += ((v0.x + v1.x) + (v2.x + v3.x)) + ((v4.x + v5.x) + (v6.x + v7.x));
            ay += ((v0.y + v1.y) + (v2.y + v3.y)) + ((v4.y + v5.y) + (v6.y + v7.y));
        }
        for (; e < en; e++) {
            float2 v = tmp2[g_esrc[e] * 32 + lane];
            ax += v.x; ay += v.y;
        }
        float dv = g_dinv[n];
        float rx = ax * dv + bx;
        float ry = ay * dv + by;
        h2[n * 32 + lane] = make_float2(rx, ry);
        s0 += rx; q0 += rx * rx;
        s1 += ry; q1 += ry * ry;
    }

    atomicAdd(&ss[2 * lane], s0);
    atomicAdd(&ss[2 * lane + 1], s1);
    atomicAdd(&sq[2 * lane], q0);
    atomicAdd(&sq[2 * lane + 1], q1);
    __syncthreads();
    if (tid < DH) {
        atomicAdd(&g_sums[statsIdx * DH + tid], ss[tid]);
        atomicAdd(&g_sumsq[statsIdx * DH + tid], sq[tid]);
    }
}

// ---------------- final: out = act(h) @ Wf^T + bf  (64 -> 10) ----------------
__global__ void final_kernel(const float* __restrict__ Wf, const float* __restrict__ bf,
                             float* __restrict__ out, int nn,
                             const float* __restrict__ gamma,
                             const float* __restrict__ beta, float invN) {
    __shared__ float Hs[64][65];
    __shared__ float Ws[10][64];
    __shared__ float s_sc[DH];
    __shared__ float s_sh[DH];
    int tid = threadIdx.x;  // 128 threads
    int br = blockIdx.x * 64;

    if (tid < DH) {
        float mean = g_sums[2 * DH + tid] * invN;
        float var = g_sumsq[2 * DH + tid] * invN - mean * mean;
        float sc = gamma[tid] * rsqrtf(var + 1e-5f);
        s_sc[tid] = sc;
        s_sh[tid] = beta[tid] - mean * sc;
    }
    __syncthreads();

    for (int idx = tid; idx < 64 * 64; idx += 128) {
        int n = idx >> 6;
        int k = idx & 63;
        int row = br + n;
        float v = (row < nn) ? g_h[row * DH + k] : 0.0f;
        Hs[n][k] = gelu_f(v * s_sc[k] + s_sh[k]);
    }
    for (int idx = tid; idx < 640; idx += 128) {
        Ws[idx >> 6][idx & 63] = Wf[idx];
    }
    __syncthreads();

    int nl = tid & 63;
    int c0 = (tid >> 6) * 5;
    float acc[5];
#pragma unroll
    for (int c = 0; c < 5; c++) acc[c] = bf[c0 + c];
#pragma unroll 16
    for (int k = 0; k < 64; k++) {
        float hv = Hs[nl][k];
#pragma unroll
        for (int c = 0; c < 5; c++) acc[c] += hv * Ws[c0 + c][k];
    }
    int row = br + nl;
    if (row < nn) {
#pragma unroll
        for (int c = 0; c < 5; c++) out[row * 10 + c0 + c] = acc[c];
    }
}

// ---------------- host orchestration ----------------
extern "C" void kernel_launch(void* const* d_in, const int* in_sizes, int n_in,
                              void* d_out, int out_size) {
    const float* x  = (const float*)d_in[0];
    const int*   ei = (const int*)d_in[1];
    const float* W1 = (const float*)d_in[2];
    const float* b1 = (const float*)d_in[3];
    const float* g1 = (const float*)d_in[4];
    const float* be1 = (const float*)d_in[5];
    const float* W2 = (const float*)d_in[6];
    const float* b2 = (const float*)d_in[7];
    const float* g2 = (const float*)d_in[8];
    const float* be2 = (const float*)d_in[9];
    const float* W3 = (const float*)d_in[10];
    const float* b3 = (const float*)d_in[11];
    const float* g3 = (const float*)d_in[12];
    const float* be3 = (const float*)d_in[13];
    const float* Wf = (const float*)d_in[14];
    const float* bf = (const float*)d_in[15];
    float* out = (float*)d_out;

    int nn = in_sizes[0] / 128;      // 100000
    int ee = in_sizes[1] / 2;        // 1600000
    const int* src = ei;
    const int* dst = ei + ee;

    int nb_e = (ee + 255) / 256;
    int nb_scan = (nn + 1023) / 1024;
    float invN = 1.0f / (float)nn;

    int gemm_blocks = (nn + 127) / 128;
    int out_blocks = (nn + 63) / 64;
    int gather_blocks = 1184;

    // ---- CSR build (also zeroes BN stats for this call) ----
    hist_kernel<<<nb_e, 256>>>(dst, ee);
    scan1_kernel<<<nb_scan, 256>>>(nn);
    scan3_kernel<<<nb_scan, 1024>>>(nn, ee, nb_scan);

    // ---- layer 1 (128 -> 64) ----
    gemm_scale_kernel<128, false, false><<<gemm_blocks, 256>>>(
        x, W1, nn, nullptr, nullptr, 0.0f, 0);
    fill_kernel<<<nb_e, 256>>>(src, dst, ee);
    gather_kernel<<<gather_blocks, 256>>>(b1, nn, 0);

    // ---- layer 2 (64 -> 64): BN1+GELU fused into X staging ----
    gemm_scale_kernel<64, true, true><<<gemm_blocks, 256>>>(
        nullptr, W2, nn, g1, be1, invN, 0);
    gather_kernel<<<gather_blocks, 256>>>(b2, nn, 1);

    // ---- layer 3 (64 -> 64): BN2+GELU fused into X staging ----
    gemm_scale_kernel<64, true, true><<<gemm_blocks, 256>>>(
        nullptr, W3, nn, g2, be2, invN, 1);
    gather_kernel<<<gather_blocks, 256>>>(b3, nn, 2);

    // ---- final classifier (64 -> 10): BN3+GELU fused into H load ----
    final_kernel<<<out_blocks, 128>>>(Wf, bf, out, nn, g3, be3, invN);
}